// round 1
// baseline (speedup 1.0000x reference)
#include <cuda_runtime.h>
#include <cstdint>

// ---------------------------------------------------------------------------
// DenseFeatureExtractionModule_AP_OS4: 10x conv3x3(+ReLU), 2x maxpool2,
// irregular mask pool, 3x mask-selected-dilation convs. fp32, FFMA2 (f32x2).
// ---------------------------------------------------------------------------

#define BATCH 4
#define TW 32
#define TH 16
#define CO_BLK 32
#define CIN_CHUNK 8
#define SH (TH + 4)
#define SWD (TW + 4)

// Ping-pong scratch (largest intermediate: 4*64*384*384 floats = 151 MB)
__device__ float g_bufA[BATCH * 64 * 384 * 384];
__device__ float g_bufB[BATCH * 64 * 384 * 384];

__device__ __forceinline__ uint64_t pack2(float v) {
    uint64_t r;
    uint32_t u = __float_as_uint(v);
    asm("mov.b64 %0, {%1, %1};" : "=l"(r) : "r"(u));
    return r;
}
__device__ __forceinline__ void fma2(uint64_t& d, uint64_t a, uint64_t b) {
    // d = a * b + d   (2 independent fp32 FMAs, sm_100+ packed pipe)
    asm("fma.rn.f32x2 %0, %1, %2, %0;" : "+l"(d) : "l"(a), "l"(b));
}

// Generic 3x3 SAME conv + bias + ReLU.
// If mask != nullptr: per-pixel dilation = 1 + mask[b][y/2][x/2] (mask at H/2 grid).
// Block: 256 threads -> tile of TH x TW output pixels, CO_BLK output channels.
// Thread: 2 pixels (rows r, r+8; same col) x 32 channels (16 f32x2 pairs each).
__global__ __launch_bounds__(256, 2)
void conv3x3_kernel(const float* __restrict__ in, const float* __restrict__ wgt,
                    const float* __restrict__ bias, const int* __restrict__ mask,
                    float* __restrict__ out, int Cin, int Cout, int H, int W)
{
    __shared__ float s_in[CIN_CHUNK][SH][SWD];
    __shared__ __align__(16) float s_w[CIN_CHUNK][9][CO_BLK];

    const int coBlocks = Cout / CO_BLK;
    const int b   = blockIdx.z / coBlocks;
    const int co0 = (blockIdx.z % coBlocks) * CO_BLK;
    const int x0  = blockIdx.x * TW;
    const int y0  = blockIdx.y * TH;

    const int tid = threadIdx.x;
    const int c   = tid & 31;        // column in tile
    const int r0  = tid >> 5;        // 0..7
    const int r1  = r0 + 8;
    const int gx  = x0 + c;
    const int gy0 = y0 + r0;
    const int gy1 = y0 + r1;

    int d0 = 1, d1 = 1;
    if (mask) {
        const int Hm = H >> 1;       // mask grid = H/2 (48 when H=96)
        d0 += mask[(b * Hm + (gy0 >> 1)) * Hm + (gx >> 1)];
        d1 += mask[(b * Hm + (gy1 >> 1)) * Hm + (gx >> 1)];
    }

    // Precompute per-pixel row/col offsets into the (halo-2) smem tile.
    int ro0[3], ro1[3], cb0[3], cb1[3];
    #pragma unroll
    for (int k = 0; k < 3; k++) {
        ro0[k] = (r0 + 2 + d0 * (k - 1)) * SWD;
        ro1[k] = (r1 + 2 + d1 * (k - 1)) * SWD;
        cb0[k] = c + 2 + d0 * (k - 1);
        cb1[k] = c + 2 + d1 * (k - 1);
    }

    uint64_t acc0[CO_BLK / 2], acc1[CO_BLK / 2];
    #pragma unroll
    for (int k = 0; k < CO_BLK / 2; k++) { acc0[k] = 0ull; acc1[k] = 0ull; }

    for (int cin0 = 0; cin0 < Cin; cin0 += CIN_CHUNK) {
        // --- stage input tile (zero-padded boundary + zero-fill past Cin) ---
        #pragma unroll 1
        for (int i = tid; i < CIN_CHUNK * SH * SWD; i += 256) {
            int ci  = i / (SH * SWD);
            int rem = i - ci * (SH * SWD);
            int iy  = rem / SWD;
            int ix  = rem - iy * SWD;
            int gyy = y0 + iy - 2;
            int gxx = x0 + ix - 2;
            int cg  = cin0 + ci;
            float v = 0.f;
            if (cg < Cin && (unsigned)gyy < (unsigned)H && (unsigned)gxx < (unsigned)W)
                v = in[((b * Cin + cg) * H + gyy) * W + gxx];
            (&s_in[0][0][0])[i] = v;
        }
        // --- stage weights: layout [ci][tap][co] so co pairs are contiguous ---
        #pragma unroll 1
        for (int i = tid; i < CIN_CHUNK * 9 * CO_BLK; i += 256) {
            int co  = i & (CO_BLK - 1);
            int tap = (i >> 5) % 9;
            int ci  = i / (9 * CO_BLK);
            int cg  = cin0 + ci;
            float v = 0.f;
            if (cg < Cin)
                v = wgt[((co0 + co) * Cin + cg) * 9 + tap];
            (&s_w[0][0][0])[i] = v;
        }
        __syncthreads();

        #pragma unroll 1
        for (int ci = 0; ci < CIN_CHUNK; ci++) {
            const float* base = &s_in[ci][0][0];
            #pragma unroll
            for (int ky = 0; ky < 3; ky++) {
                #pragma unroll
                for (int kx = 0; kx < 3; kx++) {
                    const int tap = ky * 3 + kx;
                    uint64_t i0 = pack2(base[ro0[ky] + cb0[kx]]);
                    uint64_t i1 = pack2(base[ro1[ky] + cb1[kx]]);
                    const ulonglong2* wp =
                        reinterpret_cast<const ulonglong2*>(&s_w[ci][tap][0]);
                    #pragma unroll
                    for (int k = 0; k < 8; k++) {
                        ulonglong2 wv = wp[k];     // LDS.128 broadcast (4 weights)
                        fma2(acc0[2 * k],     i0, wv.x);
                        fma2(acc0[2 * k + 1], i0, wv.y);
                        fma2(acc1[2 * k],     i1, wv.x);
                        fma2(acc1[2 * k + 1], i1, wv.y);
                    }
                }
            }
        }
        __syncthreads();
    }

    // --- epilogue: unpack pairs, + bias, ReLU, store ---
    #pragma unroll
    for (int k = 0; k < CO_BLK / 2; k++) {
        const int co_a = co0 + 2 * k;
        const int co_b = co_a + 1;
        const float ba = bias[co_a];
        const float bb = bias[co_b];
        float v;
        v = fmaxf(__uint_as_float((uint32_t)acc0[k]) + ba, 0.f);
        out[((b * Cout + co_a) * H + gy0) * W + gx] = v;
        v = fmaxf(__uint_as_float((uint32_t)(acc0[k] >> 32)) + bb, 0.f);
        out[((b * Cout + co_b) * H + gy0) * W + gx] = v;
        v = fmaxf(__uint_as_float((uint32_t)acc1[k]) + ba, 0.f);
        out[((b * Cout + co_a) * H + gy1) * W + gx] = v;
        v = fmaxf(__uint_as_float((uint32_t)(acc1[k] >> 32)) + bb, 0.f);
        out[((b * Cout + co_b) * H + gy1) * W + gx] = v;
    }
}

// 2x2 stride-2 max pool
__global__ void maxpool2_kernel(const float* __restrict__ in, float* __restrict__ out,
                                int total, int Ho, int Wo)
{
    int i = blockIdx.x * blockDim.x + threadIdx.x;
    if (i >= total) return;
    int x  = i % Wo;
    int t  = i / Wo;
    int y  = t % Ho;
    int bc = t / Ho;
    int Wi = Wo * 2;
    const float* p = in + (bc * Ho * 2 + y * 2) * Wi + x * 2;
    out[i] = fmaxf(fmaxf(p[0], p[1]), fmaxf(p[Wi], p[Wi + 1]));
}

// Irregular pool: where mask==1, each 2x2 block <- max of block (replicated);
// where mask==0, identity. H = 96, mask at H/2 = 48 grid.
__global__ void irrpool_kernel(const float* __restrict__ in, const int* __restrict__ mask,
                               float* __restrict__ out, int C, int H, int total)
{
    int i = blockIdx.x * blockDim.x + threadIdx.x;
    if (i >= total) return;
    int Hb = H >> 1;
    int bx = i % Hb;
    int t  = i / Hb;
    int by = t % Hb;
    int bc = t / Hb;          // b*C + ch
    int b  = bc / C;
    int m  = mask[(b * Hb + by) * Hb + bx];
    const float* p = in  + (bc * H + by * 2) * H + bx * 2;
    float*       q = out + (bc * H + by * 2) * H + bx * 2;
    float v00 = p[0], v01 = p[1], v10 = p[H], v11 = p[H + 1];
    if (m) {
        float mx = fmaxf(fmaxf(v00, v01), fmaxf(v10, v11));
        v00 = v01 = v10 = v11 = mx;
    }
    q[0] = v00; q[1] = v01; q[H] = v10; q[H + 1] = v11;
}

static inline void launch_conv(const float* in, const float* w, const float* b,
                               const int* mask, float* out,
                               int Cin, int Cout, int H, int W)
{
    dim3 grid(W / TW, H / TH, BATCH * (Cout / CO_BLK));
    conv3x3_kernel<<<grid, 256>>>(in, w, b, mask, out, Cin, Cout, H, W);
}

extern "C" void kernel_launch(void* const* d_in, const int* in_sizes, int n_in,
                              void* d_out, int out_size)
{
    (void)in_sizes; (void)n_in; (void)out_size;
    const float* batch = (const float*)d_in[0];
    const int*   mask  = (const int*)d_in[1];
    const float* Wt[10];
    const float* Bs[10];
    for (int i = 0; i < 10; i++) {
        Wt[i] = (const float*)d_in[2 + 2 * i];
        Bs[i] = (const float*)d_in[3 + 2 * i];
    }

    float *A, *Bf;
    cudaGetSymbolAddress((void**)&A,  g_bufA);
    cudaGetSymbolAddress((void**)&Bf, g_bufB);
    float* O = (float*)d_out;

    // Stage 1: 384x384
    launch_conv(batch, Wt[0], Bs[0], nullptr, A,  3,   64, 384, 384);
    launch_conv(A,     Wt[1], Bs[1], nullptr, Bf, 64,  64, 384, 384);
    { int tot = BATCH * 64 * 192 * 192;
      maxpool2_kernel<<<(tot + 255) / 256, 256>>>(Bf, A, tot, 192, 192); }

    // Stage 2: 192x192
    launch_conv(A,  Wt[2], Bs[2], nullptr, Bf, 64,  128, 192, 192);
    launch_conv(Bf, Wt[3], Bs[3], nullptr, A,  128, 128, 192, 192);
    { int tot = BATCH * 128 * 96 * 96;
      maxpool2_kernel<<<(tot + 255) / 256, 256>>>(A, Bf, tot, 96, 96); }

    // Stage 3: 96x96 (OS4)
    launch_conv(Bf, Wt[4], Bs[4], nullptr, A,  128, 256, 96, 96);
    launch_conv(A,  Wt[5], Bs[5], nullptr, Bf, 256, 256, 96, 96);
    launch_conv(Bf, Wt[6], Bs[6], nullptr, A,  256, 256, 96, 96);

    // Irregular pool (mask-gated 2x2 max, replicated)
    { int tot = BATCH * 256 * 48 * 48;
      irrpool_kernel<<<(tot + 255) / 256, 256>>>(A, mask, Bf, 256, 96, tot); }

    // Graph convs: per-pixel dilation = 1 + mask
    launch_conv(Bf, Wt[7], Bs[7], mask, A,  256, 512, 96, 96);
    launch_conv(A,  Wt[8], Bs[8], mask, Bf, 512, 512, 96, 96);
    launch_conv(Bf, Wt[9], Bs[9], mask, O,  512, 512, 96, 96);
}

// round 2
// speedup vs baseline: 1.0034x; 1.0034x over previous
#include <cuda_runtime.h>
#include <cstdint>

// ---------------------------------------------------------------------------
// DenseFeatureExtractionModule_AP_OS4: 10x conv3x3(+ReLU), 2x maxpool2,
// irregular mask pool, 3x mask-selected-dilation convs. fp32, FFMA2 (f32x2).
// ---------------------------------------------------------------------------

#define BATCH 4
#define TW 32
#define TH 16
#define CO_BLK 32
#define CIN_CHUNK 8
#define SH (TH + 4)
#define SWD (TW + 4)

// Ping-pong scratch (largest intermediate: 4*64*384*384 floats = 151 MB)
__device__ float g_bufA[BATCH * 64 * 384 * 384];
__device__ float g_bufB[BATCH * 64 * 384 * 384];

__device__ __forceinline__ uint64_t pack2(float v) {
    uint64_t r;
    uint32_t u = __float_as_uint(v);
    asm("mov.b64 %0, {%1, %1};" : "=l"(r) : "r"(u));
    return r;
}
__device__ __forceinline__ void fma2(uint64_t& d, uint64_t a, uint64_t b) {
    // d = a * b + d   (2 independent fp32 FMAs, sm_100+ packed pipe)
    asm("fma.rn.f32x2 %0, %1, %2, %0;" : "+l"(d) : "l"(a), "l"(b));
}

// Generic 3x3 SAME conv + bias + ReLU.
// If mask != nullptr: per-pixel dilation = 1 + mask[b][y/2][x/2] (mask at H/2 grid).
// Block: 256 threads -> tile of TH x TW output pixels, CO_BLK output channels.
// Thread: 2 pixels (rows r, r+8; same col) x 32 channels (16 f32x2 pairs each).
__global__ __launch_bounds__(256, 2)
void conv3x3_kernel(const float* __restrict__ in, const float* __restrict__ wgt,
                    const float* __restrict__ bias, const int* __restrict__ mask,
                    float* __restrict__ out, int Cin, int Cout, int H, int W)
{
    __shared__ float s_in[CIN_CHUNK][SH][SWD];
    __shared__ __align__(16) float s_w[CIN_CHUNK][9][CO_BLK];

    const int coBlocks = Cout / CO_BLK;
    const int b   = blockIdx.z / coBlocks;
    const int co0 = (blockIdx.z % coBlocks) * CO_BLK;
    const int x0  = blockIdx.x * TW;
    const int y0  = blockIdx.y * TH;

    const int tid = threadIdx.x;
    const int c   = tid & 31;        // column in tile
    const int r0  = tid >> 5;        // 0..7
    const int r1  = r0 + 8;
    const int gx  = x0 + c;
    const int gy0 = y0 + r0;
    const int gy1 = y0 + r1;

    int d0 = 1, d1 = 1;
    if (mask) {
        const int Hm = H >> 1;       // mask grid = H/2 (48 when H=96)
        d0 += mask[(b * Hm + (gy0 >> 1)) * Hm + (gx >> 1)];
        d1 += mask[(b * Hm + (gy1 >> 1)) * Hm + (gx >> 1)];
    }

    // Precompute per-pixel row/col offsets into the (halo-2) smem tile.
    int ro0[3], ro1[3], cb0[3], cb1[3];
    #pragma unroll
    for (int k = 0; k < 3; k++) {
        ro0[k] = (r0 + 2 + d0 * (k - 1)) * SWD;
        ro1[k] = (r1 + 2 + d1 * (k - 1)) * SWD;
        cb0[k] = c + 2 + d0 * (k - 1);
        cb1[k] = c + 2 + d1 * (k - 1);
    }

    uint64_t acc0[CO_BLK / 2], acc1[CO_BLK / 2];
    #pragma unroll
    for (int k = 0; k < CO_BLK / 2; k++) { acc0[k] = 0ull; acc1[k] = 0ull; }

    for (int cin0 = 0; cin0 < Cin; cin0 += CIN_CHUNK) {
        // --- stage input tile (zero-padded boundary + zero-fill past Cin) ---
        #pragma unroll 1
        for (int i = tid; i < CIN_CHUNK * SH * SWD; i += 256) {
            int ci  = i / (SH * SWD);
            int rem = i - ci * (SH * SWD);
            int iy  = rem / SWD;
            int ix  = rem - iy * SWD;
            int gyy = y0 + iy - 2;
            int gxx = x0 + ix - 2;
            int cg  = cin0 + ci;
            float v = 0.f;
            if (cg < Cin && (unsigned)gyy < (unsigned)H && (unsigned)gxx < (unsigned)W)
                v = in[((b * Cin + cg) * H + gyy) * W + gxx];
            (&s_in[0][0][0])[i] = v;
        }
        // --- stage weights: layout [ci][tap][co] so co pairs are contiguous ---
        #pragma unroll 1
        for (int i = tid; i < CIN_CHUNK * 9 * CO_BLK; i += 256) {
            int co  = i & (CO_BLK - 1);
            int tap = (i >> 5) % 9;
            int ci  = i / (9 * CO_BLK);
            int cg  = cin0 + ci;
            float v = 0.f;
            if (cg < Cin)
                v = wgt[((co0 + co) * Cin + cg) * 9 + tap];
            (&s_w[0][0][0])[i] = v;
        }
        __syncthreads();

        #pragma unroll 1
        for (int ci = 0; ci < CIN_CHUNK; ci++) {
            const float* base = &s_in[ci][0][0];
            #pragma unroll
            for (int ky = 0; ky < 3; ky++) {
                #pragma unroll
                for (int kx = 0; kx < 3; kx++) {
                    const int tap = ky * 3 + kx;
                    uint64_t i0 = pack2(base[ro0[ky] + cb0[kx]]);
                    uint64_t i1 = pack2(base[ro1[ky] + cb1[kx]]);
                    const ulonglong2* wp =
                        reinterpret_cast<const ulonglong2*>(&s_w[ci][tap][0]);
                    #pragma unroll
                    for (int k = 0; k < 8; k++) {
                        ulonglong2 wv = wp[k];     // LDS.128 broadcast (4 weights)
                        fma2(acc0[2 * k],     i0, wv.x);
                        fma2(acc0[2 * k + 1], i0, wv.y);
                        fma2(acc1[2 * k],     i1, wv.x);
                        fma2(acc1[2 * k + 1], i1, wv.y);
                    }
                }
            }
        }
        __syncthreads();
    }

    // --- epilogue: unpack pairs, + bias, ReLU, store ---
    #pragma unroll
    for (int k = 0; k < CO_BLK / 2; k++) {
        const int co_a = co0 + 2 * k;
        const int co_b = co_a + 1;
        const float ba = bias[co_a];
        const float bb = bias[co_b];
        float v;
        v = fmaxf(__uint_as_float((uint32_t)acc0[k]) + ba, 0.f);
        out[((b * Cout + co_a) * H + gy0) * W + gx] = v;
        v = fmaxf(__uint_as_float((uint32_t)(acc0[k] >> 32)) + bb, 0.f);
        out[((b * Cout + co_b) * H + gy0) * W + gx] = v;
        v = fmaxf(__uint_as_float((uint32_t)acc1[k]) + ba, 0.f);
        out[((b * Cout + co_a) * H + gy1) * W + gx] = v;
        v = fmaxf(__uint_as_float((uint32_t)(acc1[k] >> 32)) + bb, 0.f);
        out[((b * Cout + co_b) * H + gy1) * W + gx] = v;
    }
}

// 2x2 stride-2 max pool
__global__ void maxpool2_kernel(const float* __restrict__ in, float* __restrict__ out,
                                int total, int Ho, int Wo)
{
    int i = blockIdx.x * blockDim.x + threadIdx.x;
    if (i >= total) return;
    int x  = i % Wo;
    int t  = i / Wo;
    int y  = t % Ho;
    int bc = t / Ho;
    int Wi = Wo * 2;
    const float* p = in + (bc * Ho * 2 + y * 2) * Wi + x * 2;
    out[i] = fmaxf(fmaxf(p[0], p[1]), fmaxf(p[Wi], p[Wi + 1]));
}

// Irregular pool: where mask==1, each 2x2 block <- max of block (replicated);
// where mask==0, identity. H = 96, mask at H/2 = 48 grid.
__global__ void irrpool_kernel(const float* __restrict__ in, const int* __restrict__ mask,
                               float* __restrict__ out, int C, int H, int total)
{
    int i = blockIdx.x * blockDim.x + threadIdx.x;
    if (i >= total) return;
    int Hb = H >> 1;
    int bx = i % Hb;
    int t  = i / Hb;
    int by = t % Hb;
    int bc = t / Hb;          // b*C + ch
    int b  = bc / C;
    int m  = mask[(b * Hb + by) * Hb + bx];
    const float* p = in  + (bc * H + by * 2) * H + bx * 2;
    float*       q = out + (bc * H + by * 2) * H + bx * 2;
    float v00 = p[0], v01 = p[1], v10 = p[H], v11 = p[H + 1];
    if (m) {
        float mx = fmaxf(fmaxf(v00, v01), fmaxf(v10, v11));
        v00 = v01 = v10 = v11 = mx;
    }
    q[0] = v00; q[1] = v01; q[H] = v10; q[H + 1] = v11;
}

static inline void launch_conv(const float* in, const float* w, const float* b,
                               const int* mask, float* out,
                               int Cin, int Cout, int H, int W)
{
    dim3 grid(W / TW, H / TH, BATCH * (Cout / CO_BLK));
    conv3x3_kernel<<<grid, 256>>>(in, w, b, mask, out, Cin, Cout, H, W);
}

extern "C" void kernel_launch(void* const* d_in, const int* in_sizes, int n_in,
                              void* d_out, int out_size)
{
    (void)in_sizes; (void)n_in; (void)out_size;
    const float* batch = (const float*)d_in[0];
    const int*   mask  = (const int*)d_in[1];
    const float* Wt[10];
    const float* Bs[10];
    for (int i = 0; i < 10; i++) {
        Wt[i] = (const float*)d_in[2 + 2 * i];
        Bs[i] = (const float*)d_in[3 + 2 * i];
    }

    float *A, *Bf;
    cudaGetSymbolAddress((void**)&A,  g_bufA);
    cudaGetSymbolAddress((void**)&Bf, g_bufB);
    float* O = (float*)d_out;

    // Stage 1: 384x384
    launch_conv(batch, Wt[0], Bs[0], nullptr, A,  3,   64, 384, 384);
    launch_conv(A,     Wt[1], Bs[1], nullptr, Bf, 64,  64, 384, 384);
    { int tot = BATCH * 64 * 192 * 192;
      maxpool2_kernel<<<(tot + 255) / 256, 256>>>(Bf, A, tot, 192, 192); }

    // Stage 2: 192x192
    launch_conv(A,  Wt[2], Bs[2], nullptr, Bf, 64,  128, 192, 192);
    launch_conv(Bf, Wt[3], Bs[3], nullptr, A,  128, 128, 192, 192);
    { int tot = BATCH * 128 * 96 * 96;
      maxpool2_kernel<<<(tot + 255) / 256, 256>>>(A, Bf, tot, 96, 96); }

    // Stage 3: 96x96 (OS4)
    launch_conv(Bf, Wt[4], Bs[4], nullptr, A,  128, 256, 96, 96);
    launch_conv(A,  Wt[5], Bs[5], nullptr, Bf, 256, 256, 96, 96);
    launch_conv(Bf, Wt[6], Bs[6], nullptr, A,  256, 256, 96, 96);

    // Irregular pool (mask-gated 2x2 max, replicated)
    { int tot = BATCH * 256 * 48 * 48;
      irrpool_kernel<<<(tot + 255) / 256, 256>>>(A, mask, Bf, 256, 96, tot); }

    // Graph convs: per-pixel dilation = 1 + mask
    launch_conv(Bf, Wt[7], Bs[7], mask, A,  256, 512, 96, 96);
    launch_conv(A,  Wt[8], Bs[8], mask, Bf, 512, 512, 96, 96);
    launch_conv(Bf, Wt[9], Bs[9], mask, O,  512, 512, 96, 96);
}

// round 6
// speedup vs baseline: 2.0803x; 2.0733x over previous
#include <cuda_runtime.h>
#include <cuda_bf16.h>
#include <cstdint>

// ============================================================================
// HMMA (mma.sync m16n8k16 bf16) implicit-GEMM conv stack, bf16x3 split
// precision, fp32 accumulate. Activations in gmem: NHWC bf16, two planes
// (hi at +0, lo at +PL). Weights pre-split to hi/lo planes, k = tap*Cin+ci.
// ============================================================================

#define BATCH 4
#define PL 37748736   // plane stride (elements): 4*384*384*64

__device__ __nv_bfloat16 g_actA[2 * PL];   // 151 MB ping (also reused as f32 NHWC scratch)
__device__ __nv_bfloat16 g_actB[2 * PL];   // 151 MB pong
__device__ __nv_bfloat16 g_wT[15261696];   // per layer: [hi plane][lo plane]

// ---------------- PTX helpers (all arch-neutral, sm_80-class) ----------------
static __device__ __forceinline__ uint32_t smem_u32(const void* p) {
    uint32_t a;
    asm("{ .reg .u64 t; cvta.to.shared.u64 t, %1; cvt.u32.u64 %0, t; }" : "=r"(a) : "l"(p));
    return a;
}
static __device__ __forceinline__ void cp16(uint32_t dst, const void* src, uint32_t sz) {
    asm volatile("cp.async.cg.shared.global [%0], [%1], 16, %2;"
                 :: "r"(dst), "l"(src), "r"(sz) : "memory");
}
#define CP_COMMIT() asm volatile("cp.async.commit_group;" ::: "memory")
#define CP_WAIT1()  asm volatile("cp.async.wait_group 1;" ::: "memory")
#define CP_WAIT0()  asm volatile("cp.async.wait_group 0;" ::: "memory")

#define LDSM_X4(r, addr) \
    asm volatile("ldmatrix.sync.aligned.m8n8.x4.shared.b16 {%0,%1,%2,%3}, [%4];" \
        : "=r"((r)[0]), "=r"((r)[1]), "=r"((r)[2]), "=r"((r)[3]) : "r"(addr))

#define MMA16816(d, a, b) \
    asm volatile("mma.sync.aligned.m16n8k16.row.col.f32.bf16.bf16.f32 " \
        "{%0,%1,%2,%3}, {%4,%5,%6,%7}, {%8,%9}, {%0,%1,%2,%3};" \
        : "+f"((d)[0]), "+f"((d)[1]), "+f"((d)[2]), "+f"((d)[3]) \
        : "r"((a)[0]), "r"((a)[1]), "r"((a)[2]), "r"((a)[3]), "r"((b)[0]), "r"((b)[1]))

// ============================================================================
// conv HMMA kernel. M tile = 128 px (8 rows x 16 cols), N tile = NT (64/128),
// K chunked by 64 (one tap-slice of 64 input channels).
// ============================================================================
template<int NT>
__global__ __launch_bounds__(256, 1)
void conv_hmma(const __nv_bfloat16* __restrict__ aHi, const __nv_bfloat16* __restrict__ aLo,
               const __nv_bfloat16* __restrict__ wHi, const __nv_bfloat16* __restrict__ wLo,
               const float* __restrict__ bias, const int* __restrict__ mask,
               __nv_bfloat16* __restrict__ oHi, __nv_bfloat16* __restrict__ oLo,
               float* __restrict__ oF32,
               int Cin, int Cout, int H, int W)
{
    extern __shared__ char smem[];
    constexpr int ABYTES = 16384;          // 128 rows x 128B (one plane)
    constexpr int BBYTES = NT * 128;
    constexpr int BUFB   = 2 * ABYTES + 2 * BBYTES;
    constexpr int NTW    = NT / 4;         // warp n extent (32 / 16)
    constexpr int NTT    = NTW / 8;        // n8 tiles per warp (4 / 2)
    constexpr int NPAIR  = NTT / 2 ? NTT / 2 : 1;

    const int tid = threadIdx.x, lane = tid & 31, wid = tid >> 5;
    const int nB = Cout / NT;
    const int b  = blockIdx.z / nB, n0 = (blockIdx.z % nB) * NT;
    const int x0 = blockIdx.x * 16, y0 = blockIdx.y * 8;
    const int K  = 9 * Cin, NC = K / 64;

    // ---- staging roles ----
    const int ap  = tid & 127;             // pixel (A row)
    const int apl = tid >> 7;              // A plane
    const int ay  = y0 + (ap >> 4), ax = x0 + (ap & 15);
    int dil = 1;
    if (mask) dil += mask[(b * (H >> 1) + (ay >> 1)) * (W >> 1) + (ax >> 1)];
    const __nv_bfloat16* aPl = apl ? aLo : aHi;

    const int  bn   = (NT == 128) ? (tid & 127) : (tid & 63);
    const int  bpl  = (NT == 128) ? (tid >> 7) : ((tid >> 6) & 1);
    const bool bact = (NT == 128) ? true : (tid < 128);
    const __nv_bfloat16* wPl = bpl ? wLo : wHi;

    const uint32_t sbase = smem_u32(smem);
    const uint32_t xrA   = (uint32_t)(ap & 7) << 4;
    const uint32_t xrB   = (uint32_t)(bn & 7) << 4;

    auto stage = [&](int c, int q) {
        const uint32_t buf = sbase + q * BUFB;
        const int kb  = c * 64;
        const int tap = kb / Cin, cb = kb - tap * Cin;
        const int yy  = ay + (tap / 3 - 1) * dil;
        const int xx  = ax + (tap % 3 - 1) * dil;
        const bool ib = (yy >= 0 && yy < H && xx >= 0 && xx < W);
        const __nv_bfloat16* srcA =
            aPl + ((size_t)(b * H + (ib ? yy : 0)) * W + (ib ? xx : 0)) * Cin + cb;
        const uint32_t sz = ib ? 16u : 0u;
        const uint32_t dA = buf + apl * ABYTES + ap * 128;
        #pragma unroll
        for (int j = 0; j < 8; j++)
            cp16(dA + ((j * 16) ^ xrA), (const char*)srcA + j * 16, sz);
        if (bact) {
            const __nv_bfloat16* srcB = wPl + (size_t)(n0 + bn) * K + kb;
            const uint32_t dB = buf + 2 * ABYTES + bpl * BBYTES + bn * 128;
            #pragma unroll
            for (int j = 0; j < 8; j++)
                cp16(dB + ((j * 16) ^ xrB), (const char*)srcB + j * 16, 16u);
        }
        CP_COMMIT();
    };

    // ---- MMA thread geometry ----
    const int wm = wid >> 2, wn = wid & 3;
    const uint32_t rx = (uint32_t)(lane & 7) << 4;
    uint32_t aRow[4], bRow[NPAIR];
    #pragma unroll
    for (int mt = 0; mt < 4; mt++)
        aRow[mt] = (uint32_t)(wm * 64 + mt * 16 + (lane & 15)) * 128;
    #pragma unroll
    for (int pr = 0; pr < NPAIR; pr++)
        bRow[pr] = (uint32_t)(wn * NTW + pr * 16 + (lane & 7) + ((lane & 16) >> 1)) * 128;

    float acc[4][NTT][4];
    #pragma unroll
    for (int mt = 0; mt < 4; mt++)
        #pragma unroll
        for (int nt = 0; nt < NTT; nt++)
            #pragma unroll
            for (int e = 0; e < 4; e++) acc[mt][nt][e] = 0.f;

    // ---- pipeline: 2-deep cp.async double buffer ----
    stage(0, 0);
    if (NC > 1) stage(1, 1); else CP_COMMIT();

    for (int c = 0; c < NC; c++) {
        if (c + 1 < NC) CP_WAIT1(); else CP_WAIT0();
        __syncthreads();

        const int q = c & 1;
        const uint32_t bAh = sbase + q * BUFB;
        const uint32_t bAl = bAh + ABYTES;
        const uint32_t bBh = bAh + 2 * ABYTES;
        const uint32_t bBl = bBh + BBYTES;

        #pragma unroll
        for (int s = 0; s < 4; s++) {
            const uint32_t cbA = (uint32_t)(s * 32) + (lane & 16);
            const uint32_t cbB = (uint32_t)(s * 32) + ((lane & 8) << 1);
            uint32_t bh[NTT][2], bl[NTT][2];
            #pragma unroll
            for (int pr = 0; pr < NPAIR; pr++) {
                uint32_t t[4];
                LDSM_X4(t, bBh + bRow[pr] + (cbB ^ rx));
                bh[2 * pr][0] = t[0]; bh[2 * pr][1] = t[1];
                bh[2 * pr + 1][0] = t[2]; bh[2 * pr + 1][1] = t[3];
                LDSM_X4(t, bBl + bRow[pr] + (cbB ^ rx));
                bl[2 * pr][0] = t[0]; bl[2 * pr][1] = t[1];
                bl[2 * pr + 1][0] = t[2]; bl[2 * pr + 1][1] = t[3];
            }
            #pragma unroll
            for (int mt = 0; mt < 4; mt++) {
                uint32_t ah[4], al[4];
                LDSM_X4(ah, bAh + aRow[mt] + (cbA ^ rx));
                #pragma unroll
                for (int nt = 0; nt < NTT; nt++) MMA16816(acc[mt][nt], ah, bh[nt]);
                #pragma unroll
                for (int nt = 0; nt < NTT; nt++) MMA16816(acc[mt][nt], ah, bl[nt]);
                LDSM_X4(al, bAl + aRow[mt] + (cbA ^ rx));
                #pragma unroll
                for (int nt = 0; nt < NTT; nt++) MMA16816(acc[mt][nt], al, bh[nt]);
            }
        }
        __syncthreads();
        if (c + 2 < NC) stage(c + 2, q);
    }

    // ---- epilogue: bias + ReLU; split hi/lo bf16 planes (or fp32 NHWC) ----
    #pragma unroll
    for (int mt = 0; mt < 4; mt++) {
        const int pbase = wm * 64 + mt * 16 + (lane >> 2);
        #pragma unroll
        for (int nt = 0; nt < NTT; nt++) {
            const int ncol = n0 + wn * NTW + nt * 8 + 2 * (lane & 3);
            const float b0v = __ldg(bias + ncol);
            const float b1v = __ldg(bias + ncol + 1);
            #pragma unroll
            for (int rh = 0; rh < 2; rh++) {
                const int p = pbase + rh * 8;
                const int y = y0 + (p >> 4), x = x0 + (p & 15);
                const size_t idx = ((size_t)(b * H + y) * W + x) * Cout + ncol;
                float v0 = fmaxf(acc[mt][nt][2 * rh] + b0v, 0.f);
                float v1 = fmaxf(acc[mt][nt][2 * rh + 1] + b1v, 0.f);
                if (oF32) {
                    *(float2*)(oF32 + idx) = make_float2(v0, v1);
                } else {
                    __nv_bfloat16 h0 = __float2bfloat16(v0);
                    __nv_bfloat16 h1 = __float2bfloat16(v1);
                    __nv_bfloat16 l0 = __float2bfloat16(v0 - __bfloat162float(h0));
                    __nv_bfloat16 l1 = __float2bfloat16(v1 - __bfloat162float(h1));
                    *(__nv_bfloat162*)(oHi + idx) = __nv_bfloat162(h0, h1);
                    *(__nv_bfloat162*)(oLo + idx) = __nv_bfloat162(l0, l1);
                }
            }
        }
    }
}

// ============================================================================
// Layer 1 (3->64, 384x384): FFMA2 direct conv -> NHWC hi/lo planes
// ============================================================================
__device__ __forceinline__ uint64_t pack2(float v) {
    uint64_t r; uint32_t u = __float_as_uint(v);
    asm("mov.b64 %0, {%1, %1};" : "=l"(r) : "r"(u));
    return r;
}
__device__ __forceinline__ void fma2(uint64_t& d, uint64_t a, uint64_t b) {
    asm("fma.rn.f32x2 %0, %1, %2, %0;" : "+l"(d) : "l"(a), "l"(b));
}

__global__ __launch_bounds__(256)
void conv1_pack_kernel(const float* __restrict__ in, const float* __restrict__ w,
                       const float* __restrict__ bias,
                       __nv_bfloat16* __restrict__ outHi, __nv_bfloat16* __restrict__ outLo)
{
    __shared__ float s_in[3][18][18];
    __shared__ __align__(16) float s_w[27][64];
    __shared__ float s_b[64];
    const int b  = blockIdx.z;
    const int x0 = blockIdx.x * 16, y0 = blockIdx.y * 16;
    const int tid = threadIdx.x;

    for (int i = tid; i < 3 * 18 * 18; i += 256) {
        int ci = i / 324, r = (i % 324) / 18, cc = i % 18;
        int gy = y0 + r - 1, gx = x0 + cc - 1;
        float v = 0.f;
        if ((unsigned)gy < 384u && (unsigned)gx < 384u)
            v = in[((b * 3 + ci) * 384 + gy) * 384 + gx];
        (&s_in[0][0][0])[i] = v;
    }
    for (int i = tid; i < 27 * 64; i += 256) {
        int co = i & 63, t = i >> 6;
        int ci = t / 9, tap = t % 9;
        s_w[t][co] = w[(co * 3 + ci) * 9 + tap];
    }
    if (tid < 64) s_b[tid] = bias[tid];
    __syncthreads();

    const int px = tid & 15, py = tid >> 4;
    uint64_t a2[32];
    #pragma unroll
    for (int k = 0; k < 32; k++) a2[k] = 0ull;
    #pragma unroll
    for (int t = 0; t < 27; t++) {
        int ci = t / 9, tap = t % 9;
        uint64_t vv = pack2(s_in[ci][py + tap / 3][px + tap % 3]);
        const ulonglong2* wp = (const ulonglong2*)&s_w[t][0];
        #pragma unroll
        for (int k = 0; k < 16; k++) {
            ulonglong2 wv = wp[k];
            fma2(a2[2 * k],     vv, wv.x);
            fma2(a2[2 * k + 1], vv, wv.y);
        }
    }
    const size_t pix = (size_t)((b * 384 + y0 + py) * 384 + x0 + px);
    uint32_t ph[32], pll[32];
    #pragma unroll
    for (int j = 0; j < 32; j++) {
        float v0 = fmaxf(__uint_as_float((uint32_t)a2[j]) + s_b[2 * j], 0.f);
        float v1 = fmaxf(__uint_as_float((uint32_t)(a2[j] >> 32)) + s_b[2 * j + 1], 0.f);
        __nv_bfloat16 h0 = __float2bfloat16(v0), h1 = __float2bfloat16(v1);
        __nv_bfloat16 l0 = __float2bfloat16(v0 - __bfloat162float(h0));
        __nv_bfloat16 l1 = __float2bfloat16(v1 - __bfloat162float(h1));
        ph[j]  = ((uint32_t)__bfloat16_as_ushort(h1) << 16) | __bfloat16_as_ushort(h0);
        pll[j] = ((uint32_t)__bfloat16_as_ushort(l1) << 16) | __bfloat16_as_ushort(l0);
    }
    uint4* dH = (uint4*)(outHi + pix * 64);
    uint4* dL = (uint4*)(outLo + pix * 64);
    #pragma unroll
    for (int j = 0; j < 8; j++) {
        dH[j] = make_uint4(ph[4 * j], ph[4 * j + 1], ph[4 * j + 2], ph[4 * j + 3]);
        dL[j] = make_uint4(pll[4 * j], pll[4 * j + 1], pll[4 * j + 2], pll[4 * j + 3]);
    }
}

// ============================================================================
// Pools on NHWC hi/lo planes
// ============================================================================
static __device__ __forceinline__ float rec(const __nv_bfloat16* h, const __nv_bfloat16* l, size_t i) {
    return __bfloat162float(h[i]) + __bfloat162float(l[i]);
}

__global__ void maxpool2_pl(const __nv_bfloat16* __restrict__ inH, const __nv_bfloat16* __restrict__ inL,
                            __nv_bfloat16* __restrict__ outH, __nv_bfloat16* __restrict__ outL,
                            int C, int Ho, int Wo, int total)
{
    int i = blockIdx.x * blockDim.x + threadIdx.x;
    if (i >= total) return;
    int c = i % C; int t = i / C;
    int xo = t % Wo; t /= Wo;
    int yo = t % Ho; int b = t / Ho;
    int Wi = Wo * 2;
    size_t base = (size_t)((b * Ho * 2 + yo * 2) * Wi + xo * 2) * C + c;
    size_t o0 = base, o1 = base + C, o2 = base + (size_t)Wi * C, o3 = o2 + C;
    size_t best = o0; float bf = rec(inH, inL, o0);
    float f;
    f = rec(inH, inL, o1); if (f > bf) { bf = f; best = o1; }
    f = rec(inH, inL, o2); if (f > bf) { bf = f; best = o2; }
    f = rec(inH, inL, o3); if (f > bf) { bf = f; best = o3; }
    outH[i] = inH[best]; outL[i] = inL[best];
}

__global__ void irrpool_pl(const __nv_bfloat16* __restrict__ inH, const __nv_bfloat16* __restrict__ inL,
                           const int* __restrict__ mask,
                           __nv_bfloat16* __restrict__ outH, __nv_bfloat16* __restrict__ outL,
                           int C, int total)
{
    int i = blockIdx.x * blockDim.x + threadIdx.x;
    if (i >= total) return;
    int c = i % C; int t = i / C;
    int bx = t % 48; t /= 48;
    int by = t % 48; int b = t / 48;
    int m = mask[(b * 48 + by) * 48 + bx];
    size_t base = (size_t)((b * 96 + by * 2) * 96 + bx * 2) * C + c;
    size_t o[4] = { base, base + C, base + (size_t)96 * C, base + (size_t)96 * C + C };
    if (m) {
        size_t best = o[0]; float bf = rec(inH, inL, o[0]);
        #pragma unroll
        for (int j = 1; j < 4; j++) {
            float f = rec(inH, inL, o[j]);
            if (f > bf) { bf = f; best = o[j]; }
        }
        __nv_bfloat16 vh = inH[best], vl = inL[best];
        #pragma unroll
        for (int j = 0; j < 4; j++) { outH[o[j]] = vh; outL[o[j]] = vl; }
    } else {
        #pragma unroll
        for (int j = 0; j < 4; j++) { outH[o[j]] = inH[o[j]]; outL[o[j]] = inL[o[j]]; }
    }
}

// ============================================================================
// Weight transform: fp32 [cout][cin][3][3] -> bf16 hi/lo planes, k = tap*Cin+ci
// ============================================================================
__global__ void wtrans_kernel(const float* __restrict__ w, __nv_bfloat16* __restrict__ hi,
                              __nv_bfloat16* __restrict__ lo, int Cin, int total)
{
    int i = blockIdx.x * blockDim.x + threadIdx.x;
    if (i >= total) return;
    int K = Cin * 9;
    int co = i / K; int r = i - co * K;
    int ci = r / 9; int tap = r % 9;
    float v = w[i];
    __nv_bfloat16 h = __float2bfloat16(v);
    __nv_bfloat16 l = __float2bfloat16(v - __bfloat162float(h));
    int oi = co * K + tap * Cin + ci;
    hi[oi] = h; lo[oi] = l;
}

// NHWC fp32 [4,96,96,512] -> NCHW fp32
__global__ void nhwc2nchw(const float* __restrict__ in, float* __restrict__ out)
{
    __shared__ float t[32][33];
    const int b = blockIdx.z;
    const int p0 = blockIdx.x * 32, c0 = blockIdx.y * 32;
    const int tx = threadIdx.x, ty = threadIdx.y;
    #pragma unroll
    for (int j = 0; j < 4; j++) {
        int row = ty * 4 + j;
        t[row][tx] = in[((size_t)b * 9216 + p0 + row) * 512 + c0 + tx];
    }
    __syncthreads();
    #pragma unroll
    for (int j = 0; j < 4; j++) {
        int row = ty * 4 + j;
        out[((size_t)b * 512 + c0 + row) * 9216 + p0 + tx] = t[tx][row];
    }
}

// ============================================================================
extern "C" void kernel_launch(void* const* d_in, const int* in_sizes, int n_in,
                              void* d_out, int out_size)
{
    (void)in_sizes; (void)n_in; (void)out_size;
    const float* batch = (const float*)d_in[0];
    const int*   mask  = (const int*)d_in[1];
    const float* Wt[10];
    const float* Bs[10];
    for (int i = 0; i < 10; i++) {
        Wt[i] = (const float*)d_in[2 + 2 * i];
        Bs[i] = (const float*)d_in[3 + 2 * i];
    }

    __nv_bfloat16 *A, *B, *WT;
    cudaGetSymbolAddress((void**)&A,  g_actA);
    cudaGetSymbolAddress((void**)&B,  g_actB);
    cudaGetSymbolAddress((void**)&WT, g_wT);
    float* O = (float*)d_out;

    static const int    cins[9]  = {64, 64, 128, 128, 256, 256, 256, 512, 512};
    static const int    couts[9] = {64, 128, 128, 256, 256, 256, 512, 512, 512};
    static const size_t offs[9]  = {0, 73728, 221184, 516096, 1105920,
                                    2285568, 3465216, 5824512, 10543104};

    for (int l = 0; l < 9; l++) {
        int total = couts[l] * cins[l] * 9;
        wtrans_kernel<<<(total + 255) / 256, 256>>>(
            Wt[l + 1], WT + offs[l], WT + offs[l] + (size_t)couts[l] * cins[l] * 9,
            cins[l], total);
    }

    conv1_pack_kernel<<<dim3(24, 24, BATCH), 256>>>(batch, Wt[0], Bs[0], A, A + PL);

    static bool attr_done = false;
    if (!attr_done) {
        cudaFuncSetAttribute(conv_hmma<128>, cudaFuncAttributeMaxDynamicSharedMemorySize, 131072);
        cudaFuncSetAttribute(conv_hmma<64>,  cudaFuncAttributeMaxDynamicSharedMemorySize, 98304);
        attr_done = true;
    }

    auto mma = [&](const __nv_bfloat16* in, int l, const float* bias, const int* mk,
                   __nv_bfloat16* outPl, float* oF, int H, int NT) {
        int Cin = cins[l], Cout = couts[l];
        dim3 g(H / 16, H / 8, BATCH * (Cout / NT));
        const __nv_bfloat16* wh = WT + offs[l];
        const __nv_bfloat16* wl = wh + (size_t)Cout * Cin * 9;
        if (NT == 128)
            conv_hmma<128><<<g, 256, 131072>>>(in, in + PL, wh, wl, bias, mk,
                outPl, outPl ? outPl + PL : nullptr, oF, Cin, Cout, H, H);
        else
            conv_hmma<64><<<g, 256, 98304>>>(in, in + PL, wh, wl, bias, mk,
                outPl, outPl ? outPl + PL : nullptr, oF, Cin, Cout, H, H);
    };

    mma(A, 0, Bs[1], nullptr, B, nullptr, 384, 64);                     // L2
    { int tot = BATCH * 192 * 192 * 64;
      maxpool2_pl<<<(tot + 255) / 256, 256>>>(B, B + PL, A, A + PL, 64, 192, 192, tot); }
    mma(A, 1, Bs[2], nullptr, B, nullptr, 192, 128);                    // L3
    mma(B, 2, Bs[3], nullptr, A, nullptr, 192, 128);                    // L4
    { int tot = BATCH * 96 * 96 * 128;
      maxpool2_pl<<<(tot + 255) / 256, 256>>>(A, A + PL, B, B + PL, 128, 96, 96, tot); }
    mma(B, 3, Bs[4], nullptr, A, nullptr, 96, 128);                     // L5
    mma(A, 4, Bs[5], nullptr, B, nullptr, 96, 128);                     // L6
    mma(B, 5, Bs[6], nullptr, A, nullptr, 96, 128);                     // L7
    { int tot = BATCH * 48 * 48 * 256;
      irrpool_pl<<<(tot + 255) / 256, 256>>>(A, A + PL, mask, B, B + PL, 256, tot); }
    mma(B, 6, Bs[7], mask, A, nullptr, 96, 128);                        // L8
    mma(A, 7, Bs[8], mask, B, nullptr, 96, 128);                        // L9
    float* fA = (float*)A;
    mma(B, 8, Bs[9], mask, nullptr, fA, 96, 128);                       // L10 -> NHWC f32
    nhwc2nchw<<<dim3(288, 16, 4), dim3(32, 8)>>>(fA, O);
}

// round 8
// speedup vs baseline: 2.3796x; 1.1439x over previous
#include <cuda_runtime.h>
#include <cuda_bf16.h>
#include <cstdint>

// ============================================================================
// HMMA (mma.sync m16n8k16 bf16) implicit-GEMM conv stack, bf16x3 split
// precision, fp32 accumulate. Activations in gmem: NHWC bf16, two planes
// (hi at +0, lo at +PL). Weights pre-split to hi/lo planes, k = tap*Cin+ci.
// M-tile = 256 px (16x16), N-tile = NT, K chunked by 32.
// ============================================================================

#define BATCH 4
#define PL 37748736   // plane stride (elements): 4*384*384*64

__device__ __nv_bfloat16 g_actA[2 * PL];   // 151 MB ping (also f32 NHWC scratch)
__device__ __nv_bfloat16 g_actB[2 * PL];   // 151 MB pong
__device__ __nv_bfloat16 g_wT[15261696];   // per layer: [hi plane][lo plane]

// ---------------- PTX helpers (arch-neutral, sm_80-class) ----------------
static __device__ __forceinline__ uint32_t smem_u32(const void* p) {
    uint32_t a;
    asm("{ .reg .u64 t; cvta.to.shared.u64 t, %1; cvt.u32.u64 %0, t; }" : "=r"(a) : "l"(p));
    return a;
}
static __device__ __forceinline__ void cp16(uint32_t dst, const void* src, uint32_t sz) {
    asm volatile("cp.async.cg.shared.global [%0], [%1], 16, %2;"
                 :: "r"(dst), "l"(src), "r"(sz) : "memory");
}
#define CP_COMMIT() asm volatile("cp.async.commit_group;" ::: "memory")
#define CP_WAIT1()  asm volatile("cp.async.wait_group 1;" ::: "memory")
#define CP_WAIT0()  asm volatile("cp.async.wait_group 0;" ::: "memory")

#define LDSM_X4(r, addr) \
    asm volatile("ldmatrix.sync.aligned.m8n8.x4.shared.b16 {%0,%1,%2,%3}, [%4];" \
        : "=r"((r)[0]), "=r"((r)[1]), "=r"((r)[2]), "=r"((r)[3]) : "r"(addr))

#define MMA16816(d, a, b) \
    asm volatile("mma.sync.aligned.m16n8k16.row.col.f32.bf16.bf16.f32 " \
        "{%0,%1,%2,%3}, {%4,%5,%6,%7}, {%8,%9}, {%0,%1,%2,%3};" \
        : "+f"((d)[0]), "+f"((d)[1]), "+f"((d)[2]), "+f"((d)[3]) \
        : "r"((a)[0]), "r"((a)[1]), "r"((a)[2]), "r"((a)[3]), "r"((b)[0]), "r"((b)[1]))

// ============================================================================
// conv HMMA kernel. M tile = 256 px (16x16), N tile = NT (64/128), K32 chunks.
// 8 warps = 4m x 2n. Rows in smem are 64 bytes (one K32 slice, one plane).
// ============================================================================
template<int NT>
__global__ __launch_bounds__(256, 1)
void conv_hmma(const __nv_bfloat16* __restrict__ aHi, const __nv_bfloat16* __restrict__ aLo,
               const __nv_bfloat16* __restrict__ wHi, const __nv_bfloat16* __restrict__ wLo,
               const float* __restrict__ bias, const int* __restrict__ mask,
               __nv_bfloat16* __restrict__ oHi, __nv_bfloat16* __restrict__ oLo,
               float* __restrict__ oF32,
               int Cin, int Cout, int H, int W)
{
    extern __shared__ char smem[];
    constexpr int ASZ = 256 * 64;          // one A plane: 256 rows x 64B
    constexpr int BSZ = NT * 64;           // one B plane
    constexpr int BUF = 2 * ASZ + 2 * BSZ;
    constexpr int Nw  = NT / 2;            // warp n extent (64 / 32)
    constexpr int NTT = Nw / 8;            // n8 tiles per warp (8 / 4)
    constexpr int NPAIR = NTT / 2;         // x4-ldmatrix pairs (4 / 2)

    const int tid = threadIdx.x, lane = tid & 31, wid = tid >> 5;
    const int nB = Cout / NT;
    const int b  = blockIdx.z / nB, n0 = (blockIdx.z % nB) * NT;
    const int x0 = blockIdx.x * 16, y0 = blockIdx.y * 16;
    const int K  = 9 * Cin, NC = K / 32;

    // ---- staging roles: one pixel per thread (both planes) ----
    const int ay = y0 + (tid >> 4), ax = x0 + (tid & 15);
    int dil = 1;
    if (mask) dil += mask[(b * (H >> 1) + (ay >> 1)) * (W >> 1) + (ax >> 1)];
    const uint32_t xsA = (uint32_t)(((tid & 7) << 3) & 48);

    const int  bn   = (NT == 128) ? (tid & 127) : (tid & 63);
    const int  bpl  = (NT == 128) ? (tid >> 7) : ((tid >> 6) & 1);
    const bool bact = (NT == 128) ? true : (tid < 128);
    const __nv_bfloat16* wPl = bpl ? wLo : wHi;
    const uint32_t xsB = (uint32_t)(((bn & 7) << 3) & 48);

    const uint32_t sbase = smem_u32(smem);

    // incremental K-walk state (advanced once per stage() call, in order)
    int scb = 0, skx = 0, sky = 0, skb = 0;

    auto stage = [&](int q) {
        const uint32_t buf = sbase + q * BUF;
        const int yy = ay + (sky - 1) * dil;
        const int xx = ax + (skx - 1) * dil;
        const bool ib = (yy >= 0 && yy < H && xx >= 0 && xx < W);
        const size_t off = ((size_t)(b * H + (ib ? yy : 0)) * W + (ib ? xx : 0)) * Cin + scb;
        const uint32_t sz = ib ? 16u : 0u;
        const uint32_t dA = buf + (uint32_t)tid * 64;
        const char* srcH = (const char*)(aHi + off);
        const char* srcL = (const char*)(aLo + off);
        #pragma unroll
        for (int j = 0; j < 4; j++)
            cp16(dA + ((j * 16) ^ xsA), srcH + j * 16, sz);
        #pragma unroll
        for (int j = 0; j < 4; j++)
            cp16(dA + ASZ + ((j * 16) ^ xsA), srcL + j * 16, sz);
        if (bact) {
            const char* srcB = (const char*)(wPl + (size_t)(n0 + bn) * K + skb);
            const uint32_t dB = buf + 2 * ASZ + bpl * BSZ + (uint32_t)bn * 64;
            #pragma unroll
            for (int j = 0; j < 4; j++)
                cp16(dB + ((j * 16) ^ xsB), srcB + j * 16, 16u);
        }
        CP_COMMIT();
        // advance K-walk
        skb += 32;
        scb += 32;
        if (scb == Cin) { scb = 0; skx++; if (skx == 3) { skx = 0; sky++; } }
    };

    // ---- MMA thread geometry: wm in 0..3 (64 rows), wn in 0..1 (Nw cols) ----
    const int wm = wid >> 1, wn = wid & 1;
    const uint32_t xr = (uint32_t)(((lane & 7) << 3) & 48);
    uint32_t aRow[4], bRow[NPAIR];
    #pragma unroll
    for (int mt = 0; mt < 4; mt++)
        aRow[mt] = (uint32_t)(wm * 64 + mt * 16 + (lane & 15)) * 64;
    #pragma unroll
    for (int pr = 0; pr < NPAIR; pr++)
        bRow[pr] = (uint32_t)(wn * Nw + pr * 16 + (lane & 7) + ((lane & 16) >> 1)) * 64;

    float acc[4][NTT][4];
    #pragma unroll
    for (int mt = 0; mt < 4; mt++)
        #pragma unroll
        for (int nt = 0; nt < NTT; nt++)
            #pragma unroll
            for (int e = 0; e < 4; e++) acc[mt][nt][e] = 0.f;

    // ---- 2-stage cp.async pipeline ----
    stage(0);
    stage(1);

    for (int c = 0; c < NC; c++) {
        if (c + 1 < NC) CP_WAIT1(); else CP_WAIT0();
        __syncthreads();

        const int q = c & 1;
        const uint32_t bA  = sbase + q * BUF;
        const uint32_t bB  = bA + 2 * ASZ;

        #pragma unroll
        for (int s = 0; s < 2; s++) {
            const uint32_t cbA = (uint32_t)(s * 32) + (lane & 16);
            const uint32_t cbB = (uint32_t)(s * 32) + ((lane & 8) << 1);
            uint32_t bh[NTT][2], bl[NTT][2];
            #pragma unroll
            for (int pr = 0; pr < NPAIR; pr++) {
                uint32_t t[4];
                LDSM_X4(t, bB + bRow[pr] + (cbB ^ xr));
                bh[2 * pr][0] = t[0]; bh[2 * pr][1] = t[1];
                bh[2 * pr + 1][0] = t[2]; bh[2 * pr + 1][1] = t[3];
                LDSM_X4(t, bB + BSZ + bRow[pr] + (cbB ^ xr));
                bl[2 * pr][0] = t[0]; bl[2 * pr][1] = t[1];
                bl[2 * pr + 1][0] = t[2]; bl[2 * pr + 1][1] = t[3];
            }
            #pragma unroll
            for (int mt = 0; mt < 4; mt++) {
                uint32_t ah[4], al[4];
                LDSM_X4(ah, bA + aRow[mt] + (cbA ^ xr));
                #pragma unroll
                for (int nt = 0; nt < NTT; nt++) MMA16816(acc[mt][nt], ah, bh[nt]);
                #pragma unroll
                for (int nt = 0; nt < NTT; nt++) MMA16816(acc[mt][nt], ah, bl[nt]);
                LDSM_X4(al, bA + ASZ + aRow[mt] + (cbA ^ xr));
                #pragma unroll
                for (int nt = 0; nt < NTT; nt++) MMA16816(acc[mt][nt], al, bh[nt]);
            }
        }
        __syncthreads();
        if (c + 2 < NC) stage(q);
    }

    // ---- epilogue: bias + ReLU; split hi/lo bf16 planes (or fp32 NHWC) ----
    #pragma unroll
    for (int nt = 0; nt < NTT; nt++) {
        const int ncol = n0 + wn * Nw + nt * 8 + 2 * (lane & 3);
        const float b0v = __ldg(bias + ncol);
        const float b1v = __ldg(bias + ncol + 1);
        #pragma unroll
        for (int mt = 0; mt < 4; mt++) {
            #pragma unroll
            for (int rh = 0; rh < 2; rh++) {
                const int p = wm * 64 + mt * 16 + (lane >> 2) + rh * 8;
                const int y = y0 + (p >> 4), x = x0 + (p & 15);
                const size_t idx = ((size_t)(b * H + y) * W + x) * Cout + ncol;
                float v0 = fmaxf(acc[mt][nt][2 * rh] + b0v, 0.f);
                float v1 = fmaxf(acc[mt][nt][2 * rh + 1] + b1v, 0.f);
                if (oF32) {
                    *(float2*)(oF32 + idx) = make_float2(v0, v1);
                } else {
                    __nv_bfloat16 h0 = __float2bfloat16(v0);
                    __nv_bfloat16 h1 = __float2bfloat16(v1);
                    __nv_bfloat16 l0 = __float2bfloat16(v0 - __bfloat162float(h0));
                    __nv_bfloat16 l1 = __float2bfloat16(v1 - __bfloat162float(h1));
                    *(__nv_bfloat162*)(oHi + idx) = __nv_bfloat162(h0, h1);
                    *(__nv_bfloat162*)(oLo + idx) = __nv_bfloat162(l0, l1);
                }
            }
        }
    }
}

// ============================================================================
// Layer 1 (3->64, 384x384): FFMA2 direct conv -> NHWC hi/lo planes
// ============================================================================
__device__ __forceinline__ uint64_t pack2(float v) {
    uint64_t r; uint32_t u = __float_as_uint(v);
    asm("mov.b64 %0, {%1, %1};" : "=l"(r) : "r"(u));
    return r;
}
__device__ __forceinline__ void fma2(uint64_t& d, uint64_t a, uint64_t b) {
    asm("fma.rn.f32x2 %0, %1, %2, %0;" : "+l"(d) : "l"(a), "l"(b));
}

__global__ __launch_bounds__(256)
void conv1_pack_kernel(const float* __restrict__ in, const float* __restrict__ w,
                       const float* __restrict__ bias,
                       __nv_bfloat16* __restrict__ outHi, __nv_bfloat16* __restrict__ outLo)
{
    __shared__ float s_in[3][18][18];
    __shared__ __align__(16) float s_w[27][64];
    __shared__ float s_b[64];
    const int b  = blockIdx.z;
    const int x0 = blockIdx.x * 16, y0 = blockIdx.y * 16;
    const int tid = threadIdx.x;

    for (int i = tid; i < 3 * 18 * 18; i += 256) {
        int ci = i / 324, r = (i % 324) / 18, cc = i % 18;
        int gy = y0 + r - 1, gx = x0 + cc - 1;
        float v = 0.f;
        if ((unsigned)gy < 384u && (unsigned)gx < 384u)
            v = in[((b * 3 + ci) * 384 + gy) * 384 + gx];
        (&s_in[0][0][0])[i] = v;
    }
    for (int i = tid; i < 27 * 64; i += 256) {
        int co = i & 63, t = i >> 6;
        int ci = t / 9, tap = t % 9;
        s_w[t][co] = w[(co * 3 + ci) * 9 + tap];
    }
    if (tid < 64) s_b[tid] = bias[tid];
    __syncthreads();

    const int px = tid & 15, py = tid >> 4;
    uint64_t a2[32];
    #pragma unroll
    for (int k = 0; k < 32; k++) a2[k] = 0ull;
    #pragma unroll
    for (int t = 0; t < 27; t++) {
        int ci = t / 9, tap = t % 9;
        uint64_t vv = pack2(s_in[ci][py + tap / 3][px + tap % 3]);
        const ulonglong2* wp = (const ulonglong2*)&s_w[t][0];
        #pragma unroll
        for (int k = 0; k < 16; k++) {
            ulonglong2 wv = wp[k];
            fma2(a2[2 * k],     vv, wv.x);
            fma2(a2[2 * k + 1], vv, wv.y);
        }
    }
    const size_t pix = (size_t)((b * 384 + y0 + py) * 384 + x0 + px);
    uint32_t ph[32], pll[32];
    #pragma unroll
    for (int j = 0; j < 32; j++) {
        float v0 = fmaxf(__uint_as_float((uint32_t)a2[j]) + s_b[2 * j], 0.f);
        float v1 = fmaxf(__uint_as_float((uint32_t)(a2[j] >> 32)) + s_b[2 * j + 1], 0.f);
        __nv_bfloat16 h0 = __float2bfloat16(v0), h1 = __float2bfloat16(v1);
        __nv_bfloat16 l0 = __float2bfloat16(v0 - __bfloat162float(h0));
        __nv_bfloat16 l1 = __float2bfloat16(v1 - __bfloat162float(h1));
        ph[j]  = ((uint32_t)__bfloat16_as_ushort(h1) << 16) | __bfloat16_as_ushort(h0);
        pll[j] = ((uint32_t)__bfloat16_as_ushort(l1) << 16) | __bfloat16_as_ushort(l0);
    }
    uint4* dH = (uint4*)(outHi + pix * 64);
    uint4* dL = (uint4*)(outLo + pix * 64);
    #pragma unroll
    for (int j = 0; j < 8; j++) {
        dH[j] = make_uint4(ph[4 * j], ph[4 * j + 1], ph[4 * j + 2], ph[4 * j + 3]);
        dL[j] = make_uint4(pll[4 * j], pll[4 * j + 1], pll[4 * j + 2], pll[4 * j + 3]);
    }
}

// ============================================================================
// Pools on NHWC hi/lo planes
// ============================================================================
static __device__ __forceinline__ float rec(const __nv_bfloat16* h, const __nv_bfloat16* l, size_t i) {
    return __bfloat162float(h[i]) + __bfloat162float(l[i]);
}

__global__ void maxpool2_pl(const __nv_bfloat16* __restrict__ inH, const __nv_bfloat16* __restrict__ inL,
                            __nv_bfloat16* __restrict__ outH, __nv_bfloat16* __restrict__ outL,
                            int C, int Ho, int Wo, int total)
{
    int i = blockIdx.x * blockDim.x + threadIdx.x;
    if (i >= total) return;
    int c = i % C; int t = i / C;
    int xo = t % Wo; t /= Wo;
    int yo = t % Ho; int b = t / Ho;
    int Wi = Wo * 2;
    size_t base = (size_t)((b * Ho * 2 + yo * 2) * Wi + xo * 2) * C + c;
    size_t o0 = base, o1 = base + C, o2 = base + (size_t)Wi * C, o3 = o2 + C;
    size_t best = o0; float bf = rec(inH, inL, o0);
    float f;
    f = rec(inH, inL, o1); if (f > bf) { bf = f; best = o1; }
    f = rec(inH, inL, o2); if (f > bf) { bf = f; best = o2; }
    f = rec(inH, inL, o3); if (f > bf) { bf = f; best = o3; }
    outH[i] = inH[best]; outL[i] = inL[best];
}

__global__ void irrpool_pl(const __nv_bfloat16* __restrict__ inH, const __nv_bfloat16* __restrict__ inL,
                           const int* __restrict__ mask,
                           __nv_bfloat16* __restrict__ outH, __nv_bfloat16* __restrict__ outL,
                           int C, int total)
{
    int i = blockIdx.x * blockDim.x + threadIdx.x;
    if (i >= total) return;
    int c = i % C; int t = i / C;
    int bx = t % 48; t /= 48;
    int by = t % 48; int b = t / 48;
    int m = mask[(b * 48 + by) * 48 + bx];
    size_t base = (size_t)((b * 96 + by * 2) * 96 + bx * 2) * C + c;
    size_t o[4] = { base, base + C, base + (size_t)96 * C, base + (size_t)96 * C + C };
    if (m) {
        size_t best = o[0]; float bf = rec(inH, inL, o[0]);
        #pragma unroll
        for (int j = 1; j < 4; j++) {
            float f = rec(inH, inL, o[j]);
            if (f > bf) { bf = f; best = o[j]; }
        }
        __nv_bfloat16 vh = inH[best], vl = inL[best];
        #pragma unroll
        for (int j = 0; j < 4; j++) { outH[o[j]] = vh; outL[o[j]] = vl; }
    } else {
        #pragma unroll
        for (int j = 0; j < 4; j++) { outH[o[j]] = inH[o[j]]; outL[o[j]] = inL[o[j]]; }
    }
}

// ============================================================================
// Weight transform: fp32 [cout][cin][3][3] -> bf16 hi/lo planes, k = tap*Cin+ci
// ============================================================================
__global__ void wtrans_kernel(const float* __restrict__ w, __nv_bfloat16* __restrict__ hi,
                              __nv_bfloat16* __restrict__ lo, int Cin, int total)
{
    int i = blockIdx.x * blockDim.x + threadIdx.x;
    if (i >= total) return;
    int K = Cin * 9;
    int co = i / K; int r = i - co * K;
    int ci = r / 9; int tap = r % 9;
    float v = w[i];
    __nv_bfloat16 h = __float2bfloat16(v);
    __nv_bfloat16 l = __float2bfloat16(v - __bfloat162float(h));
    int oi = co * K + tap * Cin + ci;
    hi[oi] = h; lo[oi] = l;
}

// NHWC fp32 [4,96,96,512] -> NCHW fp32
__global__ void nhwc2nchw(const float* __restrict__ in, float* __restrict__ out)
{
    __shared__ float t[32][33];
    const int b = blockIdx.z;
    const int p0 = blockIdx.x * 32, c0 = blockIdx.y * 32;
    const int tx = threadIdx.x, ty = threadIdx.y;
    #pragma unroll
    for (int j = 0; j < 4; j++) {
        int row = ty * 4 + j;
        t[row][tx] = in[((size_t)b * 9216 + p0 + row) * 512 + c0 + tx];
    }
    __syncthreads();
    #pragma unroll
    for (int j = 0; j < 4; j++) {
        int row = ty * 4 + j;
        out[((size_t)b * 512 + c0 + row) * 9216 + p0 + tx] = t[tx][row];
    }
}

// ============================================================================
extern "C" void kernel_launch(void* const* d_in, const int* in_sizes, int n_in,
                              void* d_out, int out_size)
{
    (void)in_sizes; (void)n_in; (void)out_size;
    const float* batch = (const float*)d_in[0];
    const int*   mask  = (const int*)d_in[1];
    const float* Wt[10];
    const float* Bs[10];
    for (int i = 0; i < 10; i++) {
        Wt[i] = (const float*)d_in[2 + 2 * i];
        Bs[i] = (const float*)d_in[3 + 2 * i];
    }

    __nv_bfloat16 *A, *B, *WT;
    cudaGetSymbolAddress((void**)&A,  g_actA);
    cudaGetSymbolAddress((void**)&B,  g_actB);
    cudaGetSymbolAddress((void**)&WT, g_wT);
    float* O = (float*)d_out;

    static const int    cins[9]  = {64, 64, 128, 128, 256, 256, 256, 512, 512};
    static const int    couts[9] = {64, 128, 128, 256, 256, 256, 512, 512, 512};
    static const size_t offs[9]  = {0, 73728, 221184, 516096, 1105920,
                                    2285568, 3465216, 5824512, 10543104};

    for (int l = 0; l < 9; l++) {
        int total = couts[l] * cins[l] * 9;
        wtrans_kernel<<<(total + 255) / 256, 256>>>(
            Wt[l + 1], WT + offs[l], WT + offs[l] + (size_t)couts[l] * cins[l] * 9,
            cins[l], total);
    }

    conv1_pack_kernel<<<dim3(24, 24, BATCH), 256>>>(batch, Wt[0], Bs[0], A, A + PL);

    cudaFuncSetAttribute(conv_hmma<128>, cudaFuncAttributeMaxDynamicSharedMemorySize, 98304);
    cudaFuncSetAttribute(conv_hmma<64>,  cudaFuncAttributeMaxDynamicSharedMemorySize, 81920);

    auto mma = [&](const __nv_bfloat16* in, int l, const float* bias, const int* mk,
                   __nv_bfloat16* outPl, float* oF, int H, int NT) {
        int Cin = cins[l], Cout = couts[l];
        dim3 g(H / 16, H / 16, BATCH * (Cout / NT));
        const __nv_bfloat16* wh = WT + offs[l];
        const __nv_bfloat16* wl = wh + (size_t)Cout * Cin * 9;
        if (NT == 128)
            conv_hmma<128><<<g, 256, 98304>>>(in, in + PL, wh, wl, bias, mk,
                outPl, outPl ? outPl + PL : nullptr, oF, Cin, Cout, H, H);
        else
            conv_hmma<64><<<g, 256, 81920>>>(in, in + PL, wh, wl, bias, mk,
                outPl, outPl ? outPl + PL : nullptr, oF, Cin, Cout, H, H);
    };

    mma(A, 0, Bs[1], nullptr, B, nullptr, 384, 64);                     // L2
    { int tot = BATCH * 192 * 192 * 64;
      maxpool2_pl<<<(tot + 255) / 256, 256>>>(B, B + PL, A, A + PL, 64, 192, 192, tot); }
    mma(A, 1, Bs[2], nullptr, B, nullptr, 192, 128);                    // L3
    mma(B, 2, Bs[3], nullptr, A, nullptr, 192, 128);                    // L4
    { int tot = BATCH * 96 * 96 * 128;
      maxpool2_pl<<<(tot + 255) / 256, 256>>>(A, A + PL, B, B + PL, 128, 96, 96, tot); }
    mma(B, 3, Bs[4], nullptr, A, nullptr, 96, 128);                     // L5
    mma(A, 4, Bs[5], nullptr, B, nullptr, 96, 128);                     // L6
    mma(B, 5, Bs[6], nullptr, A, nullptr, 96, 128);                     // L7
    { int tot = BATCH * 48 * 48 * 256;
      irrpool_pl<<<(tot + 255) / 256, 256>>>(A, A + PL, mask, B, B + PL, 256, tot); }
    mma(B, 6, Bs[7], mask, A, nullptr, 96, 128);                        // L8
    mma(A, 7, Bs[8], mask, B, nullptr, 96, 128);                        // L9
    float* fA = (float*)A;
    mma(B, 8, Bs[9], mask, nullptr, fA, 96, 128);                       // L10 -> NHWC f32
    nhwc2nchw<<<dim3(288, 16, 4), dim3(32, 8)>>>(fA, O);
}

// round 11
// speedup vs baseline: 2.6278x; 1.1043x over previous
#include <cuda_runtime.h>
#include <cuda_bf16.h>
#include <cstdint>

// ============================================================================
// HMMA (mma.sync m16n8k16 bf16) implicit-GEMM conv stack, bf16x3 split
// precision, fp32 accumulate. Activations in gmem: NHWC bf16, two planes
// (hi at +0, lo at +PL). Weights pre-split to hi/lo planes, k = tap*Cin+ci.
// M-tile = 256 px (16x16), N-tile = NT, K chunked by 32, 512 threads,
// 3-stage cp.async pipeline with one __syncthreads per chunk.
// ============================================================================

#define BATCH 4
#define PL 37748736   // plane stride (elements): 4*384*384*64

__device__ __nv_bfloat16 g_actA[2 * PL];   // 151 MB ping (also f32 NHWC scratch)
__device__ __nv_bfloat16 g_actB[2 * PL];   // 151 MB pong
__device__ __nv_bfloat16 g_wT[15261696];   // per layer: [hi plane][lo plane]

// ---------------- PTX helpers (arch-neutral, sm_80-class) ----------------
static __device__ __forceinline__ uint32_t smem_u32(const void* p) {
    uint32_t a;
    asm("{ .reg .u64 t; cvta.to.shared.u64 t, %1; cvt.u32.u64 %0, t; }" : "=r"(a) : "l"(p));
    return a;
}
static __device__ __forceinline__ void cp16(uint32_t dst, const void* src, uint32_t sz) {
    asm volatile("cp.async.cg.shared.global [%0], [%1], 16, %2;"
                 :: "r"(dst), "l"(src), "r"(sz) : "memory");
}
#define CP_COMMIT() asm volatile("cp.async.commit_group;" ::: "memory")
#define CP_WAIT1()  asm volatile("cp.async.wait_group 1;" ::: "memory")
#define CP_WAIT0()  asm volatile("cp.async.wait_group 0;" ::: "memory")

#define LDSM_X4(r, addr) \
    asm volatile("ldmatrix.sync.aligned.m8n8.x4.shared.b16 {%0,%1,%2,%3}, [%4];" \
        : "=r"((r)[0]), "=r"((r)[1]), "=r"((r)[2]), "=r"((r)[3]) : "r"(addr))

#define MMA16816(d, a, b) \
    asm volatile("mma.sync.aligned.m16n8k16.row.col.f32.bf16.bf16.f32 " \
        "{%0,%1,%2,%3}, {%4,%5,%6,%7}, {%8,%9}, {%0,%1,%2,%3};" \
        : "+f"((d)[0]), "+f"((d)[1]), "+f"((d)[2]), "+f"((d)[3]) \
        : "r"((a)[0]), "r"((a)[1]), "r"((a)[2]), "r"((a)[3]), "r"((b)[0]), "r"((b)[1]))

// ============================================================================
// conv HMMA kernel. M tile = 256 px (16x16), N tile = NT (64/128), K32 chunks.
// 16 warps = 4m x 4n. Rows in smem are 64 bytes (one K32 slice, one plane).
// 3 smem stages.
// ============================================================================
template<int NT>
__global__ __launch_bounds__(512, 1)
void conv_hmma(const __nv_bfloat16* __restrict__ aHi, const __nv_bfloat16* __restrict__ aLo,
               const __nv_bfloat16* __restrict__ wHi, const __nv_bfloat16* __restrict__ wLo,
               const float* __restrict__ bias, const int* __restrict__ mask,
               __nv_bfloat16* __restrict__ oHi, __nv_bfloat16* __restrict__ oLo,
               float* __restrict__ oF32,
               int Cin, int Cout, int H, int W)
{
    extern __shared__ char smem[];
    constexpr int ASZ = 256 * 64;          // one A plane: 256 rows x 64B
    constexpr int BSZ = NT * 64;           // one B plane
    constexpr int BUF = 2 * ASZ + 2 * BSZ;
    constexpr int Nw  = NT / 4;            // warp n extent (32 / 16)
    constexpr int NTT = Nw / 8;            // n8 tiles per warp (4 / 2)
    constexpr int NPAIR = NTT / 2;         // x4-ldmatrix pairs (2 / 1)
    constexpr int BTASK = NT * 4;          // half-row staging tasks (2 planes)

    const int tid = threadIdx.x, lane = tid & 31, wid = tid >> 5;
    const int nB = Cout / NT;
    const int b  = blockIdx.z / nB, n0 = (blockIdx.z % nB) * NT;
    const int x0 = blockIdx.x * 16, y0 = blockIdx.y * 16;
    const int K  = 9 * Cin, NC = K / 32;

    // ---- A staging role: pixel = tid&255, plane = tid>>8 ----
    const int apix = tid & 255, apl = tid >> 8;
    const int ay = y0 + (apix >> 4), ax = x0 + (apix & 15);
    int dil = 1;
    if (mask) dil += mask[(b * (H >> 1) + (ay >> 1)) * (W >> 1) + (ax >> 1)];
    const __nv_bfloat16* aPl = apl ? aLo : aHi;
    const uint32_t xsA = (uint32_t)(((apix & 7) << 3) & 48);

    // ---- B staging role: half-rows; task = (plane*NT + bn)*2 + half ----
    const bool bact = (tid < BTASK);
    const int  bhalf = tid & 1;
    const int  bn    = (tid >> 1) & (NT - 1);
    const int  bpl   = (NT == 128) ? (tid >> 8) : ((tid >> 7) & 1);
    const __nv_bfloat16* wPl = bpl ? wLo : wHi;
    const uint32_t xsB = (uint32_t)(((bn & 7) << 3) & 48);

    const uint32_t sbase = smem_u32(smem);

    // incremental K-walk state (advanced once per stage() call, in order)
    int scb = 0, skx = 0, sky = 0, skb = 0;

    auto stage = [&](int q) {
        const uint32_t buf = sbase + q * BUF;
        const int yy = ay + (sky - 1) * dil;
        const int xx = ax + (skx - 1) * dil;
        const bool ib = (yy >= 0 && yy < H && xx >= 0 && xx < W);
        const size_t off = ((size_t)(b * H + (ib ? yy : 0)) * W + (ib ? xx : 0)) * Cin + scb;
        const uint32_t sz = ib ? 16u : 0u;
        const uint32_t dA = buf + apl * ASZ + (uint32_t)apix * 64;
        const char* srcA = (const char*)(aPl + off);
        #pragma unroll
        for (int j = 0; j < 4; j++)
            cp16(dA + ((j * 16) ^ xsA), srcA + j * 16, sz);
        if (bact) {
            const char* srcB = (const char*)(wPl + (size_t)(n0 + bn) * K + skb) + bhalf * 32;
            const uint32_t dB = buf + 2 * ASZ + bpl * BSZ + (uint32_t)bn * 64;
            #pragma unroll
            for (int j = 0; j < 2; j++)
                cp16(dB + (((bhalf * 32) + j * 16) ^ xsB), srcB + j * 16, 16u);
        }
        CP_COMMIT();
        // advance K-walk
        skb += 32;
        scb += 32;
        if (scb == Cin) { scb = 0; skx++; if (skx == 3) { skx = 0; sky++; } }
    };

    // ---- MMA thread geometry: wm in 0..3 (64 rows), wn in 0..3 (Nw cols) ----
    const int wm = wid >> 2, wn = wid & 3;
    const uint32_t xr = (uint32_t)(((lane & 7) << 3) & 48);
    uint32_t aRow[4], bRow[NPAIR];
    #pragma unroll
    for (int mt = 0; mt < 4; mt++)
        aRow[mt] = (uint32_t)(wm * 64 + mt * 16 + (lane & 15)) * 64;
    #pragma unroll
    for (int pr = 0; pr < NPAIR; pr++)
        bRow[pr] = (uint32_t)(wn * Nw + pr * 16 + (lane & 7) + ((lane & 16) >> 1)) * 64;

    float acc[4][NTT][4];
    #pragma unroll
    for (int mt = 0; mt < 4; mt++)
        #pragma unroll
        for (int nt = 0; nt < NTT; nt++)
            #pragma unroll
            for (int e = 0; e < 4; e++) acc[mt][nt][e] = 0.f;

    // ---- 3-stage cp.async pipeline, one sync per chunk ----
    stage(0);
    stage(1);

    for (int c = 0; c < NC; c++) {
        if (c + 1 < NC) CP_WAIT1(); else CP_WAIT0();
        __syncthreads();
        if (c + 2 < NC) stage((c + 2) % 3);   // overlaps with MMA below

        const uint32_t bA = sbase + (c % 3) * BUF;
        const uint32_t bB = bA + 2 * ASZ;

        #pragma unroll
        for (int s = 0; s < 2; s++) {
            const uint32_t cbA = (uint32_t)(s * 32) + (lane & 16);
            const uint32_t cbB = (uint32_t)(s * 32) + ((lane & 8) << 1);
            uint32_t bh[NTT][2], bl[NTT][2];
            #pragma unroll
            for (int pr = 0; pr < NPAIR; pr++) {
                uint32_t t[4];
                LDSM_X4(t, bB + bRow[pr] + (cbB ^ xr));
                bh[2 * pr][0] = t[0]; bh[2 * pr][1] = t[1];
                bh[2 * pr + 1][0] = t[2]; bh[2 * pr + 1][1] = t[3];
                LDSM_X4(t, bB + BSZ + bRow[pr] + (cbB ^ xr));
                bl[2 * pr][0] = t[0]; bl[2 * pr][1] = t[1];
                bl[2 * pr + 1][0] = t[2]; bl[2 * pr + 1][1] = t[3];
            }
            #pragma unroll
            for (int mt = 0; mt < 4; mt++) {
                uint32_t ah[4], al[4];
                LDSM_X4(ah, bA + aRow[mt] + (cbA ^ xr));
                #pragma unroll
                for (int nt = 0; nt < NTT; nt++) MMA16816(acc[mt][nt], ah, bh[nt]);
                #pragma unroll
                for (int nt = 0; nt < NTT; nt++) MMA16816(acc[mt][nt], ah, bl[nt]);
                LDSM_X4(al, bA + ASZ + aRow[mt] + (cbA ^ xr));
                #pragma unroll
                for (int nt = 0; nt < NTT; nt++) MMA16816(acc[mt][nt], al, bh[nt]);
            }
        }
    }

    // ---- epilogue: bias + ReLU; split hi/lo bf16 planes (or fp32 NHWC) ----
    #pragma unroll
    for (int nt = 0; nt < NTT; nt++) {
        const int ncol = n0 + wn * Nw + nt * 8 + 2 * (lane & 3);
        const float b0v = __ldg(bias + ncol);
        const float b1v = __ldg(bias + ncol + 1);
        #pragma unroll
        for (int mt = 0; mt < 4; mt++) {
            #pragma unroll
            for (int rh = 0; rh < 2; rh++) {
                const int p = wm * 64 + mt * 16 + (lane >> 2) + rh * 8;
                const int y = y0 + (p >> 4), x = x0 + (p & 15);
                const size_t idx = ((size_t)(b * H + y) * W + x) * Cout + ncol;
                float v0 = fmaxf(acc[mt][nt][2 * rh] + b0v, 0.f);
                float v1 = fmaxf(acc[mt][nt][2 * rh + 1] + b1v, 0.f);
                if (oF32) {
                    *(float2*)(oF32 + idx) = make_float2(v0, v1);
                } else {
                    __nv_bfloat16 h0 = __float2bfloat16(v0);
                    __nv_bfloat16 h1 = __float2bfloat16(v1);
                    __nv_bfloat16 l0 = __float2bfloat16(v0 - __bfloat162float(h0));
                    __nv_bfloat16 l1 = __float2bfloat16(v1 - __bfloat162float(h1));
                    *(__nv_bfloat162*)(oHi + idx) = __nv_bfloat162(h0, h1);
                    *(__nv_bfloat162*)(oLo + idx) = __nv_bfloat162(l0, l1);
                }
            }
        }
    }
}

// ============================================================================
// Layer 1 (3->64, 384x384): FFMA2 direct conv -> NHWC hi/lo planes
// ============================================================================
__device__ __forceinline__ uint64_t pack2(float v) {
    uint64_t r; uint32_t u = __float_as_uint(v);
    asm("mov.b64 %0, {%1, %1};" : "=l"(r) : "r"(u));
    return r;
}
__device__ __forceinline__ void fma2(uint64_t& d, uint64_t a, uint64_t b) {
    asm("fma.rn.f32x2 %0, %1, %2, %0;" : "+l"(d) : "l"(a), "l"(b));
}

__global__ __launch_bounds__(256)
void conv1_pack_kernel(const float* __restrict__ in, const float* __restrict__ w,
                       const float* __restrict__ bias,
                       __nv_bfloat16* __restrict__ outHi, __nv_bfloat16* __restrict__ outLo)
{
    __shared__ float s_in[3][18][18];
    __shared__ __align__(16) float s_w[27][64];
    __shared__ float s_b[64];
    const int b  = blockIdx.z;
    const int x0 = blockIdx.x * 16, y0 = blockIdx.y * 16;
    const int tid = threadIdx.x;

    for (int i = tid; i < 3 * 18 * 18; i += 256) {
        int ci = i / 324, r = (i % 324) / 18, cc = i % 18;
        int gy = y0 + r - 1, gx = x0 + cc - 1;
        float v = 0.f;
        if ((unsigned)gy < 384u && (unsigned)gx < 384u)
            v = in[((b * 3 + ci) * 384 + gy) * 384 + gx];
        (&s_in[0][0][0])[i] = v;
    }
    for (int i = tid; i < 27 * 64; i += 256) {
        int co = i & 63, t = i >> 6;
        int ci = t / 9, tap = t % 9;
        s_w[t][co] = w[(co * 3 + ci) * 9 + tap];
    }
    if (tid < 64) s_b[tid] = bias[tid];
    __syncthreads();

    const int px = tid & 15, py = tid >> 4;
    uint64_t a2[32];
    #pragma unroll
    for (int k = 0; k < 32; k++) a2[k] = 0ull;
    #pragma unroll
    for (int t = 0; t < 27; t++) {
        int ci = t / 9, tap = t % 9;
        uint64_t vv = pack2(s_in[ci][py + tap / 3][px + tap % 3]);
        const ulonglong2* wp = (const ulonglong2*)&s_w[t][0];
        #pragma unroll
        for (int k = 0; k < 16; k++) {
            ulonglong2 wv = wp[k];
            fma2(a2[2 * k],     vv, wv.x);
            fma2(a2[2 * k + 1], vv, wv.y);
        }
    }
    const size_t pix = (size_t)((b * 384 + y0 + py) * 384 + x0 + px);
    uint32_t ph[32], pll[32];
    #pragma unroll
    for (int j = 0; j < 32; j++) {
        float v0 = fmaxf(__uint_as_float((uint32_t)a2[j]) + s_b[2 * j], 0.f);
        float v1 = fmaxf(__uint_as_float((uint32_t)(a2[j] >> 32)) + s_b[2 * j + 1], 0.f);
        __nv_bfloat16 h0 = __float2bfloat16(v0), h1 = __float2bfloat16(v1);
        __nv_bfloat16 l0 = __float2bfloat16(v0 - __bfloat162float(h0));
        __nv_bfloat16 l1 = __float2bfloat16(v1 - __bfloat162float(h1));
        ph[j]  = ((uint32_t)__bfloat16_as_ushort(h1) << 16) | __bfloat16_as_ushort(h0);
        pll[j] = ((uint32_t)__bfloat16_as_ushort(l1) << 16) | __bfloat16_as_ushort(l0);
    }
    uint4* dH = (uint4*)(outHi + pix * 64);
    uint4* dL = (uint4*)(outLo + pix * 64);
    #pragma unroll
    for (int j = 0; j < 8; j++) {
        dH[j] = make_uint4(ph[4 * j], ph[4 * j + 1], ph[4 * j + 2], ph[4 * j + 3]);
        dL[j] = make_uint4(pll[4 * j], pll[4 * j + 1], pll[4 * j + 2], pll[4 * j + 3]);
    }
}

// ============================================================================
// Pools on NHWC hi/lo planes
// ============================================================================
static __device__ __forceinline__ float rec(const __nv_bfloat16* h, const __nv_bfloat16* l, size_t i) {
    return __bfloat162float(h[i]) + __bfloat162float(l[i]);
}

__global__ void maxpool2_pl(const __nv_bfloat16* __restrict__ inH, const __nv_bfloat16* __restrict__ inL,
                            __nv_bfloat16* __restrict__ outH, __nv_bfloat16* __restrict__ outL,
                            int C, int Ho, int Wo, int total)
{
    int i = blockIdx.x * blockDim.x + threadIdx.x;
    if (i >= total) return;
    int c = i % C; int t = i / C;
    int xo = t % Wo; t /= Wo;
    int yo = t % Ho; int b = t / Ho;
    int Wi = Wo * 2;
    size_t base = (size_t)((b * Ho * 2 + yo * 2) * Wi + xo * 2) * C + c;
    size_t o0 = base, o1 = base + C, o2 = base + (size_t)Wi * C, o3 = o2 + C;
    size_t best = o0; float bf = rec(inH, inL, o0);
    float f;
    f = rec(inH, inL, o1); if (f > bf) { bf = f; best = o1; }
    f = rec(inH, inL, o2); if (f > bf) { bf = f; best = o2; }
    f = rec(inH, inL, o3); if (f > bf) { bf = f; best = o3; }
    outH[i] = inH[best]; outL[i] = inL[best];
}

__global__ void irrpool_pl(const __nv_bfloat16* __restrict__ inH, const __nv_bfloat16* __restrict__ inL,
                           const int* __restrict__ mask,
                           __nv_bfloat16* __restrict__ outH, __nv_bfloat16* __restrict__ outL,
                           int C, int total)
{
    int i = blockIdx.x * blockDim.x + threadIdx.x;
    if (i >= total) return;
    int c = i % C; int t = i / C;
    int bx = t % 48; t /= 48;
    int by = t % 48; int b = t / 48;
    int m = mask[(b * 48 + by) * 48 + bx];
    size_t base = (size_t)((b * 96 + by * 2) * 96 + bx * 2) * C + c;
    size_t o[4] = { base, base + C, base + (size_t)96 * C, base + (size_t)96 * C + C };
    if (m) {
        size_t best = o[0]; float bf = rec(inH, inL, o[0]);
        #pragma unroll
        for (int j = 1; j < 4; j++) {
            float f = rec(inH, inL, o[j]);
            if (f > bf) { bf = f; best = o[j]; }
        }
        __nv_bfloat16 vh = inH[best], vl = inL[best];
        #pragma unroll
        for (int j = 0; j < 4; j++) { outH[o[j]] = vh; outL[o[j]] = vl; }
    } else {
        #pragma unroll
        for (int j = 0; j < 4; j++) { outH[o[j]] = inH[o[j]]; outL[o[j]] = inL[o[j]]; }
    }
}

// ============================================================================
// Weight transform: fp32 [cout][cin][3][3] -> bf16 hi/lo planes, k = tap*Cin+ci
// ============================================================================
__global__ void wtrans_kernel(const float* __restrict__ w, __nv_bfloat16* __restrict__ hi,
                              __nv_bfloat16* __restrict__ lo, int Cin, int total)
{
    int i = blockIdx.x * blockDim.x + threadIdx.x;
    if (i >= total) return;
    int K = Cin * 9;
    int co = i / K; int r = i - co * K;
    int ci = r / 9; int tap = r % 9;
    float v = w[i];
    __nv_bfloat16 h = __float2bfloat16(v);
    __nv_bfloat16 l = __float2bfloat16(v - __bfloat162float(h));
    int oi = co * K + tap * Cin + ci;
    hi[oi] = h; lo[oi] = l;
}

// NHWC fp32 [4,96,96,512] -> NCHW fp32
__global__ void nhwc2nchw(const float* __restrict__ in, float* __restrict__ out)
{
    __shared__ float t[32][33];
    const int b = blockIdx.z;
    const int p0 = blockIdx.x * 32, c0 = blockIdx.y * 32;
    const int tx = threadIdx.x, ty = threadIdx.y;
    #pragma unroll
    for (int j = 0; j < 4; j++) {
        int row = ty * 4 + j;
        t[row][tx] = in[((size_t)b * 9216 + p0 + row) * 512 + c0 + tx];
    }
    __syncthreads();
    #pragma unroll
    for (int j = 0; j < 4; j++) {
        int row = ty * 4 + j;
        out[((size_t)b * 512 + c0 + row) * 9216 + p0 + tx] = t[tx][row];
    }
}

// ============================================================================
extern "C" void kernel_launch(void* const* d_in, const int* in_sizes, int n_in,
                              void* d_out, int out_size)
{
    (void)in_sizes; (void)n_in; (void)out_size;
    const float* batch = (const float*)d_in[0];
    const int*   mask  = (const int*)d_in[1];
    const float* Wt[10];
    const float* Bs[10];
    for (int i = 0; i < 10; i++) {
        Wt[i] = (const float*)d_in[2 + 2 * i];
        Bs[i] = (const float*)d_in[3 + 2 * i];
    }

    __nv_bfloat16 *A, *B, *WT;
    cudaGetSymbolAddress((void**)&A,  g_actA);
    cudaGetSymbolAddress((void**)&B,  g_actB);
    cudaGetSymbolAddress((void**)&WT, g_wT);
    float* O = (float*)d_out;

    static const int    cins[9]  = {64, 64, 128, 128, 256, 256, 256, 512, 512};
    static const int    couts[9] = {64, 128, 128, 256, 256, 256, 512, 512, 512};
    static const size_t offs[9]  = {0, 73728, 221184, 516096, 1105920,
                                    2285568, 3465216, 5824512, 10543104};

    for (int l = 0; l < 9; l++) {
        int total = couts[l] * cins[l] * 9;
        wtrans_kernel<<<(total + 255) / 256, 256>>>(
            Wt[l + 1], WT + offs[l], WT + offs[l] + (size_t)couts[l] * cins[l] * 9,
            cins[l], total);
    }

    conv1_pack_kernel<<<dim3(24, 24, BATCH), 256>>>(batch, Wt[0], Bs[0], A, A + PL);

    // smem: NT=128 -> 3*(2*16384+2*8192)=147456 ; NT=64 -> 3*(32768+8192)=122880
    cudaFuncSetAttribute(conv_hmma<128>, cudaFuncAttributeMaxDynamicSharedMemorySize, 147456);
    cudaFuncSetAttribute(conv_hmma<64>,  cudaFuncAttributeMaxDynamicSharedMemorySize, 122880);

    auto mma = [&](const __nv_bfloat16* in, int l, const float* bias, const int* mk,
                   __nv_bfloat16* outPl, float* oF, int H, int NT) {
        int Cin = cins[l], Cout = couts[l];
        dim3 g(H / 16, H / 16, BATCH * (Cout / NT));
        const __nv_bfloat16* wh = WT + offs[l];
        const __nv_bfloat16* wl = wh + (size_t)Cout * Cin * 9;
        if (NT == 128)
            conv_hmma<128><<<g, 512, 147456>>>(in, in + PL, wh, wl, bias, mk,
                outPl, outPl ? outPl + PL : nullptr, oF, Cin, Cout, H, H);
        else
            conv_hmma<64><<<g, 512, 122880>>>(in, in + PL, wh, wl, bias, mk,
                outPl, outPl ? outPl + PL : nullptr, oF, Cin, Cout, H, H);
    };

    mma(A, 0, Bs[1], nullptr, B, nullptr, 384, 64);                     // L2
    { int tot = BATCH * 192 * 192 * 64;
      maxpool2_pl<<<(tot + 255) / 256, 256>>>(B, B + PL, A, A + PL, 64, 192, 192, tot); }
    mma(A, 1, Bs[2], nullptr, B, nullptr, 192, 128);                    // L3
    mma(B, 2, Bs[3], nullptr, A, nullptr, 192, 128);                    // L4
    { int tot = BATCH * 96 * 96 * 128;
      maxpool2_pl<<<(tot + 255) / 256, 256>>>(A, A + PL, B, B + PL, 128, 96, 96, tot); }
    mma(B, 3, Bs[4], nullptr, A, nullptr, 96, 128);                     // L5
    mma(A, 4, Bs[5], nullptr, B, nullptr, 96, 128);                     // L6
    mma(B, 5, Bs[6], nullptr, A, nullptr, 96, 128);                     // L7
    { int tot = BATCH * 48 * 48 * 256;
      irrpool_pl<<<(tot + 255) / 256, 256>>>(A, A + PL, mask, B, B + PL, 256, tot); }
    mma(B, 6, Bs[7], mask, A, nullptr, 96, 128);                        // L8
    mma(A, 7, Bs[8], mask, B, nullptr, 96, 128);                        // L9
    float* fA = (float*)A;
    mma(B, 8, Bs[9], mask, nullptr, fA, 96, 128);                       // L10 -> NHWC f32
    nhwc2nchw<<<dim3(288, 16, 4), dim3(32, 8)>>>(fA, O);
}